// round 8
// baseline (speedup 1.0000x reference)
#include <cuda_runtime.h>

// Router: logits = x @ wg^T + gr @ gm^T ; std-normalized softmax; top-2;
// mask expert E-1; renormalize.
// Output layout (float32): [gates 2T | indices 2T | logits 8T]
//
// R8: R7 was warp-starved (14 warps/SM, issue 26%, all pipes <60%).
// Same pipeline, but NT=4 tokens/warp and ONE 896-thread CTA per SM
// -> 28 warps/SM at the same 176KB smem footprint (ring stage halves
// to 2KB). 4096 units, one per warp, ~99% balance. launch_bounds
// caps regs at 72 (acc is only 16 regs with NT=4).

constexpr int D       = 2048;
constexpr int E       = 8;
constexpr int NT      = 4;            // tokens per warp
constexpr int THREADS = 896;          // 28 warps, 1 CTA/SM
constexpr int WARPS   = THREADS / 32;
constexpr int CHUNKS  = D / 4;        // 16B chunks per row = 512
constexpr int ITERS   = CHUNKS / 32;  // 16 iterations (32 chunks each)
constexpr int DEPTH   = 2;            // cp.async stages (2KB each)
constexpr int GRID    = 148;          // 1 CTA per SM

// smem floats: wg [E*D] | gm [64] | x-ring [WARPS*DEPTH*NT*128]
constexpr int XOFF_FLOATS = E * D + 64;                         // 16448
constexpr int X_FLOATS    = WARPS * DEPTH * NT * 128;           // 28672
constexpr int SMEM_BYTES  = (XOFF_FLOATS + X_FLOATS) * 4;       // 180480 B

__device__ __forceinline__ unsigned long long ffma2(unsigned long long a,
                                                    unsigned long long b,
                                                    unsigned long long c) {
    unsigned long long d;
    asm("fma.rn.f32x2 %0, %1, %2, %3;" : "=l"(d) : "l"(a), "l"(b), "l"(c));
    return d;
}

__device__ __forceinline__ float pairsum(unsigned long long v) {
    float2 f;
    f.x = __uint_as_float((unsigned int)(v & 0xffffffffull));
    f.y = __uint_as_float((unsigned int)(v >> 32));
    return f.x + f.y;
}

__device__ __forceinline__ void cp16(unsigned int dst_smem, const void* src) {
    asm volatile("cp.async.cg.shared.global [%0], [%1], 16;\n"
                 :: "r"(dst_smem), "l"(src) : "memory");
}

__global__ void __launch_bounds__(THREADS, 1)
router_kernel(const float* __restrict__ x,
              const float* __restrict__ wg,
              const float* __restrict__ gm,
              const float* __restrict__ gr,
              float* __restrict__ out_gates,
              float* __restrict__ out_idx,
              float* __restrict__ out_logits,
              int nGroups) {
    extern __shared__ float smem[];
    float4* s_wg4 = reinterpret_cast<float4*>(smem);            // [E][D]
    float*  s_gm  = smem + E * D;                               // [E][E]

    const float4* wg4 = reinterpret_cast<const float4*>(wg);
    for (int i = threadIdx.x; i < E * CHUNKS; i += THREADS) s_wg4[i] = wg4[i];
    if (threadIdx.x < E * E) s_gm[threadIdx.x] = gm[threadIdx.x];
    __syncthreads();

    const ulonglong2* s_w2 = reinterpret_cast<const ulonglong2*>(smem);

    const int lane = threadIdx.x & 31;
    const int wid  = threadIdx.x >> 5;
    const int l8   = lane & 7;        // position within octet
    const int e0   = (lane >> 3) * 2; // this octet's first expert

    // Per-warp private x staging ring: DEPTH stages of NT*32 16B chunks.
    ulonglong2* s_x2 = reinterpret_cast<ulonglong2*>(smem + XOFF_FLOATS)
                       + wid * (DEPTH * NT * 32);
    const unsigned int xs_addr =
        (unsigned int)__cvta_generic_to_shared(s_x2) + lane * 16;

    // one unit per warp; CTAs 0-99 have 28 busy warps, 100-147 have 27
    const int g = blockIdx.x + gridDim.x * wid;

    if (g < nGroups) {
        const int t0 = g * NT;
        const char* xrow = reinterpret_cast<const char*>(x + (size_t)t0 * D);

        unsigned long long acc[NT][2];
        #pragma unroll
        for (int j = 0; j < NT; j++) { acc[j][0] = 0ull; acc[j][1] = 0ull; }

        // ---- prologue: stages 0..DEPTH-1 ----
        #pragma unroll
        for (int s = 0; s < DEPTH; s++) {
            const unsigned int dst = xs_addr + s * (NT * 512);
            const char* src = xrow + s * 512 + lane * 16;
            #pragma unroll
            for (int j = 0; j < NT; j++)
                cp16(dst + j * 512, src + (size_t)j * (D * 4));
            asm volatile("cp.async.commit_group;\n" ::: "memory");
        }

        #pragma unroll 2
        for (int it = 0; it < ITERS; it++) {
            // pending <= DEPTH-1  =>  stage `it` has landed.
            asm volatile("cp.async.wait_group %0;\n" :: "n"(DEPTH - 1) : "memory");

            const ulonglong2* xs = s_x2 + (it & (DEPTH - 1)) * (NT * 32);

            #pragma unroll
            for (int k = 0; k < 4; k++) {
                const int c = it * 32 + l8 + k * 8;
                ulonglong2 wv0 = s_w2[e0 * CHUNKS + c];
                ulonglong2 wv1 = s_w2[(e0 + 1) * CHUNKS + c];
                #pragma unroll
                for (int j = 0; j < NT; j++) {
                    ulonglong2 xv = xs[j * 32 + l8 + k * 8];
                    acc[j][0] = ffma2(xv.x, wv0.x, acc[j][0]);
                    acc[j][0] = ffma2(xv.y, wv0.y, acc[j][0]);
                    acc[j][1] = ffma2(xv.x, wv1.x, acc[j][1]);
                    acc[j][1] = ffma2(xv.y, wv1.y, acc[j][1]);
                }
            }

            // refill slot (it % DEPTH) with stage it+DEPTH — strictly AFTER
            // the reads above (consumed again only at iter it+DEPTH).
            const int s = it + DEPTH;
            if (s < ITERS) {
                const unsigned int dst = xs_addr + (it & (DEPTH - 1)) * (NT * 512);
                const char* src = xrow + s * 512 + lane * 16;
                #pragma unroll
                for (int j = 0; j < NT; j++)
                    cp16(dst + j * 512, src + (size_t)j * (D * 4));
            }
            asm volatile("cp.async.commit_group;\n" ::: "memory");
        }

        // ---- reduce within each octet (3-step butterfly) ----
        float red[NT][2];
        #pragma unroll
        for (int j = 0; j < NT; j++) {
            #pragma unroll
            for (int e = 0; e < 2; e++) {
                float s = pairsum(acc[j][e]);
                s += __shfl_xor_sync(0xffffffffu, s, 4);
                s += __shfl_xor_sync(0xffffffffu, s, 2);
                s += __shfl_xor_sync(0xffffffffu, s, 1);
                red[j][e] = s;
            }
        }

        // lane (octet q, l8=j<NT) keeps token t0+j's logits for experts
        // 2q, 2q+1; gather all 8 experts onto lanes 0-3.
        float s0 = red[0][0], s1 = red[0][1];
        #pragma unroll
        for (int jj = 1; jj < NT; jj++)
            if (l8 == jj) { s0 = red[jj][0]; s1 = red[jj][1]; }

        float logit[E];
        logit[0] = s0;
        logit[1] = s1;
        logit[2] = __shfl_sync(0xffffffffu, s0, l8 + 8);
        logit[3] = __shfl_sync(0xffffffffu, s1, l8 + 8);
        logit[4] = __shfl_sync(0xffffffffu, s0, l8 + 16);
        logit[5] = __shfl_sync(0xffffffffu, s1, l8 + 16);
        logit[6] = __shfl_sync(0xffffffffu, s0, l8 + 24);
        logit[7] = __shfl_sync(0xffffffffu, s1, l8 + 24);

        if (lane < NT) {
            const int t = t0 + lane;

            float4 g0 = __ldg(reinterpret_cast<const float4*>(gr + (size_t)t * E));
            float4 g1 = __ldg(reinterpret_cast<const float4*>(gr + (size_t)t * E + 4));
            float grv[8] = {g0.x, g0.y, g0.z, g0.w, g1.x, g1.y, g1.z, g1.w};
            float lg[E];
            #pragma unroll
            for (int f = 0; f < E; f++) {
                float s = logit[f];
                #pragma unroll
                for (int e = 0; e < E; e++) s = fmaf(grv[e], s_gm[f * E + e], s);
                lg[f] = s;
            }

            // unbiased std (ddof=1) over E=8
            float mean = 0.f;
            #pragma unroll
            for (int f = 0; f < E; f++) mean += lg[f];
            mean *= (1.f / E);
            float var = 0.f;
            #pragma unroll
            for (int f = 0; f < E; f++) {
                float d = lg[f] - mean;
                var = fmaf(d, d, var);
            }
            float inv_std = rsqrtf(var * (1.f / (E - 1)));

            float z[E], m = -3.402823466e+38f;
            #pragma unroll
            for (int f = 0; f < E; f++) {
                z[f] = lg[f] * inv_std;
                m = fmaxf(m, z[f]);
            }
            float p[E], psum = 0.f;
            #pragma unroll
            for (int f = 0; f < E; f++) {
                p[f] = __expf(z[f] - m);
                psum += p[f];
            }
            float inv_psum = 1.f / psum;
            #pragma unroll
            for (int f = 0; f < E; f++) p[f] *= inv_psum;

            // stable top-2 (descending, lower index wins ties)
            int i1 = 0; float v1 = p[0];
            #pragma unroll
            for (int f = 1; f < E; f++)
                if (p[f] > v1) { v1 = p[f]; i1 = f; }
            int i2; float v2;
            if (i1 == 0) { i2 = 1; v2 = p[1]; } else { i2 = 0; v2 = p[0]; }
            #pragma unroll
            for (int f = 1; f < E; f++)
                if (f != i1 && p[f] > v2) { v2 = p[f]; i2 = f; }

            float gg1 = (i1 == E - 1) ? 0.f : v1;
            float gg2 = (i2 == E - 1) ? 0.f : v2;
            float inv_s = 1.f / (gg1 + gg2);
            gg1 *= inv_s; gg2 *= inv_s;

            float2 gpair; gpair.x = gg1; gpair.y = gg2;
            *reinterpret_cast<float2*>(out_gates + (size_t)2 * t) = gpair;
            float2 ipair; ipair.x = (float)i1; ipair.y = (float)i2;
            *reinterpret_cast<float2*>(out_idx + (size_t)2 * t) = ipair;

            float4 L0; L0.x = lg[0]; L0.y = lg[1]; L0.z = lg[2]; L0.w = lg[3];
            float4 L1; L1.x = lg[4]; L1.y = lg[5]; L1.z = lg[6]; L1.w = lg[7];
            float4* olr = reinterpret_cast<float4*>(out_logits + (size_t)t * E);
            olr[0] = L0;
            olr[1] = L1;
        }

        asm volatile("cp.async.wait_group 0;\n" ::: "memory");
    }
}

extern "C" void kernel_launch(void* const* d_in, const int* in_sizes, int n_in,
                              void* d_out, int out_size) {
    const float* x  = (const float*)d_in[0];   // [T, D]
    const float* wg = (const float*)d_in[1];   // [E, D]
    const float* gm = (const float*)d_in[2];   // [E, E]
    const float* gr = (const float*)d_in[3];   // [T, E]

    const int T = in_sizes[0] / D;
    float* out       = (float*)d_out;
    float* out_gates = out;                       // [T,2]
    float* out_idx   = out + (size_t)2 * T;       // [T,2] as float
    float* out_logit = out + (size_t)4 * T;       // [T,8]

    cudaFuncSetAttribute(router_kernel,
                         cudaFuncAttributeMaxDynamicSharedMemorySize,
                         SMEM_BYTES);

    const int nGroups = T / NT;                   // 4096
    router_kernel<<<GRID, THREADS, SMEM_BYTES>>>(x, wg, gm, gr,
                                                 out_gates, out_idx, out_logit,
                                                 nGroups);
}

// round 9
// speedup vs baseline: 1.0289x; 1.0289x over previous
#include <cuda_runtime.h>

// Router: logits = x @ wg^T + gr @ gm^T ; std-normalized softmax; top-2;
// mask expert E-1; renormalize.
// Output layout (float32): [gates 2T | indices 2T | logits 8T]
//
// R9: R8 was L1-pipe bound (69%), dominated by the cp.async ring
// (LDGSTS = 8cy/op) + x LDS read-back. Fix: drop the ring; each lane
// LDGs x[tok j][it*32+k*8+l8] directly -- all 4 octets read the SAME
// 128B line per token row (coalescer dedup, nL=1) so x arrives in
// registers at 1 wavefront/line while the expert-octet split keeps
// accumulators at 16 regs. L1 work drops ~22.5us -> ~12us, below the
// ~17us DRAM floor.

constexpr int D       = 2048;
constexpr int E       = 8;
constexpr int NT      = 4;            // tokens per warp
constexpr int THREADS = 896;          // 28 warps, 1 CTA/SM
constexpr int WARPS   = THREADS / 32;
constexpr int CHUNKS  = D / 4;        // 16B chunks per row = 512
constexpr int ITERS   = CHUNKS / 32;  // 16 iterations (32 chunks each)
constexpr int GRID    = 148;          // 1 CTA per SM

constexpr int SMEM_BYTES = (E * D + 64) * 4;   // wg + gm = 65792 B

__device__ __forceinline__ unsigned long long ffma2(unsigned long long a,
                                                    unsigned long long b,
                                                    unsigned long long c) {
    unsigned long long d;
    asm("fma.rn.f32x2 %0, %1, %2, %3;" : "=l"(d) : "l"(a), "l"(b), "l"(c));
    return d;
}

__device__ __forceinline__ float pairsum(unsigned long long v) {
    float2 f;
    f.x = __uint_as_float((unsigned int)(v & 0xffffffffull));
    f.y = __uint_as_float((unsigned int)(v >> 32));
    return f.x + f.y;
}

__global__ void __launch_bounds__(THREADS, 1)
router_kernel(const float* __restrict__ x,
              const float* __restrict__ wg,
              const float* __restrict__ gm,
              const float* __restrict__ gr,
              float* __restrict__ out_gates,
              float* __restrict__ out_idx,
              float* __restrict__ out_logits,
              int nGroups) {
    extern __shared__ float smem[];
    float4* s_wg4 = reinterpret_cast<float4*>(smem);            // [E][D]
    float*  s_gm  = smem + E * D;                               // [E][E]

    const float4* wg4 = reinterpret_cast<const float4*>(wg);
    for (int i = threadIdx.x; i < E * CHUNKS; i += THREADS) s_wg4[i] = wg4[i];
    if (threadIdx.x < E * E) s_gm[threadIdx.x] = gm[threadIdx.x];
    __syncthreads();

    const ulonglong2* s_w2 = reinterpret_cast<const ulonglong2*>(smem);

    const int lane = threadIdx.x & 31;
    const int wid  = threadIdx.x >> 5;
    const int l8   = lane & 7;        // position within octet
    const int e0   = (lane >> 3) * 2; // this octet's first expert

    // one unit per warp; 148x28 = 4144 warps cover 4096 units
    const int g = blockIdx.x + gridDim.x * wid;

    if (g < nGroups) {
        const int t0 = g * NT;
        const ulonglong2* xr =
            reinterpret_cast<const ulonglong2*>(x + (size_t)t0 * D);
        // token j's chunk c lives at xr[j*CHUNKS + c]

        unsigned long long acc[NT][2];
        #pragma unroll
        for (int j = 0; j < NT; j++) { acc[j][0] = 0ull; acc[j][1] = 0ull; }

        #pragma unroll 2
        for (int it = 0; it < ITERS; it++) {
            #pragma unroll
            for (int k = 0; k < 4; k++) {
                const int c = it * 32 + k * 8 + l8;
                // each LDG touches ONE 128B line per token row (octets
                // read identical addresses -> warp-level dedup)
                ulonglong2 xv0 = __ldcs(xr + 0 * CHUNKS + c);
                ulonglong2 xv1 = __ldcs(xr + 1 * CHUNKS + c);
                ulonglong2 xv2 = __ldcs(xr + 2 * CHUNKS + c);
                ulonglong2 xv3 = __ldcs(xr + 3 * CHUNKS + c);
                ulonglong2 wv0 = s_w2[e0 * CHUNKS + c];
                ulonglong2 wv1 = s_w2[(e0 + 1) * CHUNKS + c];
                acc[0][0] = ffma2(xv0.x, wv0.x, acc[0][0]);
                acc[0][0] = ffma2(xv0.y, wv0.y, acc[0][0]);
                acc[0][1] = ffma2(xv0.x, wv1.x, acc[0][1]);
                acc[0][1] = ffma2(xv0.y, wv1.y, acc[0][1]);
                acc[1][0] = ffma2(xv1.x, wv0.x, acc[1][0]);
                acc[1][0] = ffma2(xv1.y, wv0.y, acc[1][0]);
                acc[1][1] = ffma2(xv1.x, wv1.x, acc[1][1]);
                acc[1][1] = ffma2(xv1.y, wv1.y, acc[1][1]);
                acc[2][0] = ffma2(xv2.x, wv0.x, acc[2][0]);
                acc[2][0] = ffma2(xv2.y, wv0.y, acc[2][0]);
                acc[2][1] = ffma2(xv2.x, wv1.x, acc[2][1]);
                acc[2][1] = ffma2(xv2.y, wv1.y, acc[2][1]);
                acc[3][0] = ffma2(xv3.x, wv0.x, acc[3][0]);
                acc[3][0] = ffma2(xv3.y, wv0.y, acc[3][0]);
                acc[3][1] = ffma2(xv3.x, wv1.x, acc[3][1]);
                acc[3][1] = ffma2(xv3.y, wv1.y, acc[3][1]);
            }
        }

        // ---- reduce within each octet (3-step butterfly) ----
        float red[NT][2];
        #pragma unroll
        for (int j = 0; j < NT; j++) {
            #pragma unroll
            for (int e = 0; e < 2; e++) {
                float s = pairsum(acc[j][e]);
                s += __shfl_xor_sync(0xffffffffu, s, 4);
                s += __shfl_xor_sync(0xffffffffu, s, 2);
                s += __shfl_xor_sync(0xffffffffu, s, 1);
                red[j][e] = s;
            }
        }

        // lane (octet q, l8=j<NT) keeps token t0+j's logits for experts
        // 2q, 2q+1; gather all 8 experts onto lanes 0-3.
        float s0 = red[0][0], s1 = red[0][1];
        #pragma unroll
        for (int jj = 1; jj < NT; jj++)
            if (l8 == jj) { s0 = red[jj][0]; s1 = red[jj][1]; }

        float logit[E];
        logit[0] = s0;
        logit[1] = s1;
        logit[2] = __shfl_sync(0xffffffffu, s0, l8 + 8);
        logit[3] = __shfl_sync(0xffffffffu, s1, l8 + 8);
        logit[4] = __shfl_sync(0xffffffffu, s0, l8 + 16);
        logit[5] = __shfl_sync(0xffffffffu, s1, l8 + 16);
        logit[6] = __shfl_sync(0xffffffffu, s0, l8 + 24);
        logit[7] = __shfl_sync(0xffffffffu, s1, l8 + 24);

        if (lane < NT) {
            const int t = t0 + lane;

            float4 g0 = __ldg(reinterpret_cast<const float4*>(gr + (size_t)t * E));
            float4 g1 = __ldg(reinterpret_cast<const float4*>(gr + (size_t)t * E + 4));
            float grv[8] = {g0.x, g0.y, g0.z, g0.w, g1.x, g1.y, g1.z, g1.w};
            float lg[E];
            #pragma unroll
            for (int f = 0; f < E; f++) {
                float s = logit[f];
                #pragma unroll
                for (int e = 0; e < E; e++) s = fmaf(grv[e], s_gm[f * E + e], s);
                lg[f] = s;
            }

            // unbiased std (ddof=1) over E=8
            float mean = 0.f;
            #pragma unroll
            for (int f = 0; f < E; f++) mean += lg[f];
            mean *= (1.f / E);
            float var = 0.f;
            #pragma unroll
            for (int f = 0; f < E; f++) {
                float d = lg[f] - mean;
                var = fmaf(d, d, var);
            }
            float inv_std = rsqrtf(var * (1.f / (E - 1)));

            float z[E], m = -3.402823466e+38f;
            #pragma unroll
            for (int f = 0; f < E; f++) {
                z[f] = lg[f] * inv_std;
                m = fmaxf(m, z[f]);
            }
            float p[E], psum = 0.f;
            #pragma unroll
            for (int f = 0; f < E; f++) {
                p[f] = __expf(z[f] - m);
                psum += p[f];
            }
            float inv_psum = 1.f / psum;
            #pragma unroll
            for (int f = 0; f < E; f++) p[f] *= inv_psum;

            // stable top-2 (descending, lower index wins ties)
            int i1 = 0; float v1 = p[0];
            #pragma unroll
            for (int f = 1; f < E; f++)
                if (p[f] > v1) { v1 = p[f]; i1 = f; }
            int i2; float v2;
            if (i1 == 0) { i2 = 1; v2 = p[1]; } else { i2 = 0; v2 = p[0]; }
            #pragma unroll
            for (int f = 1; f < E; f++)
                if (f != i1 && p[f] > v2) { v2 = p[f]; i2 = f; }

            float gg1 = (i1 == E - 1) ? 0.f : v1;
            float gg2 = (i2 == E - 1) ? 0.f : v2;
            float inv_s = 1.f / (gg1 + gg2);
            gg1 *= inv_s; gg2 *= inv_s;

            float2 gpair; gpair.x = gg1; gpair.y = gg2;
            *reinterpret_cast<float2*>(out_gates + (size_t)2 * t) = gpair;
            float2 ipair; ipair.x = (float)i1; ipair.y = (float)i2;
            *reinterpret_cast<float2*>(out_idx + (size_t)2 * t) = ipair;

            float4 L0; L0.x = lg[0]; L0.y = lg[1]; L0.z = lg[2]; L0.w = lg[3];
            float4 L1; L1.x = lg[4]; L1.y = lg[5]; L1.z = lg[6]; L1.w = lg[7];
            float4* olr = reinterpret_cast<float4*>(out_logits + (size_t)t * E);
            olr[0] = L0;
            olr[1] = L1;
        }
    }
}

extern "C" void kernel_launch(void* const* d_in, const int* in_sizes, int n_in,
                              void* d_out, int out_size) {
    const float* x  = (const float*)d_in[0];   // [T, D]
    const float* wg = (const float*)d_in[1];   // [E, D]
    const float* gm = (const float*)d_in[2];   // [E, E]
    const float* gr = (const float*)d_in[3];   // [T, E]

    const int T = in_sizes[0] / D;
    float* out       = (float*)d_out;
    float* out_gates = out;                       // [T,2]
    float* out_idx   = out + (size_t)2 * T;       // [T,2] as float
    float* out_logit = out + (size_t)4 * T;       // [T,8]

    cudaFuncSetAttribute(router_kernel,
                         cudaFuncAttributeMaxDynamicSharedMemorySize,
                         SMEM_BYTES);

    const int nGroups = T / NT;                   // 4096
    router_kernel<<<GRID, THREADS, SMEM_BYTES>>>(x, wg, gm, gr,
                                                 out_gates, out_idx, out_logit,
                                                 nGroups);
}